// round 8
// baseline (speedup 1.0000x reference)
#include <cuda_runtime.h>
#include <cstdint>

// ---------------------------------------------------------------------------
// GenerativeUpsample: per-batch kth-smallest threshold on pred, prune fea.
//   fea:  [N, 64] f32   d_in[0]
//   pred: [N, 1]  f32   d_in[1]
//   bid:  [N]     i32   d_in[2]  (sorted)
//   tgt:  [B]     i32   d_in[3]
// out: [N*64] pruned fea, then (if room) [N] keep as 0/1 float.
//
// Exact 2-level (16+16 bit) radix select on monotone uint key of pred.
// coarse+walk fused via ticket (threadFenceReduction pattern): last 8 blocks
// perform the per-batch scan-select walk in-kernel. 6 launches total.
// ---------------------------------------------------------------------------

#define MAXB 8
#define NBIN 65536
#define NSEG 64
#define SEGBINS 1024

__device__ __align__(16) unsigned g_hist1[MAXB * NBIN];
__device__ __align__(16) unsigned g_hist2[MAXB * NBIN];
__device__ unsigned g_seg[MAXB * NSEG];
__device__ unsigned g_ticket;          // monotone within one invocation
__device__ int      g_off[MAXB + 1];
__device__ unsigned g_selBin[MAXB];
__device__ unsigned g_selRank[MAXB];
__device__ int      g_active[MAXB];
__device__ unsigned g_threshKey[MAXB];

__device__ __forceinline__ unsigned f2key(float f) {
    unsigned u = __float_as_uint(f);
    return (u & 0x80000000u) ? ~u : (u | 0x80000000u);
}

__device__ __forceinline__ int batch_of(int i, const int* o) {
    int b = 0;
    #pragma unroll
    for (int k = 1; k < MAXB; k++) b += (i >= o[k]);
    return b;
}

// block-wide (256 thr) exclusive scan; wsum = 8-word smem scratch.
__device__ __forceinline__ unsigned scan_excl(unsigned val, int tid,
                                              unsigned* wsum) {
    int lane = tid & 31, wid = tid >> 5;
    unsigned x = val;
    #pragma unroll
    for (int d = 1; d < 32; d <<= 1) {
        unsigned y = __shfl_up_sync(0xFFFFFFFFu, x, d);
        if (lane >= d) x += y;
    }
    if (lane == 31) wsum[wid] = x;
    __syncthreads();
    if (tid == 0) {
        unsigned a = 0;
        #pragma unroll
        for (int w = 0; w < 8; w++) { unsigned t = wsum[w]; wsum[w] = a; a += t; }
    }
    __syncthreads();
    return wsum[wid] + x - val;
}

// -------- batch boundaries via binary search (bids sorted) -----------------
__global__ void k_bounds(const int* __restrict__ bid, int n) {
    int t = threadIdx.x;
    if (t > MAXB) return;
    if (t == MAXB) { g_off[MAXB] = n; return; }
    int lo = 0, hi = n;
    while (lo < hi) {
        int mid = (lo + hi) >> 1;
        if (bid[mid] < t) lo = mid + 1; else hi = mid;
    }
    g_off[t] = lo;
}

// -------- pass 1: top-16-bit histogram, float4 loads -----------------------
__global__ void k_hist1(const float4* __restrict__ pred4, int n4) {
    __shared__ int soff[MAXB + 1];
    if (threadIdx.x <= MAXB) soff[threadIdx.x] = g_off[threadIdx.x];
    __syncthreads();
    int o[MAXB + 1];
    #pragma unroll
    for (int k = 0; k <= MAXB; k++) o[k] = soff[k];

    for (int i4 = blockIdx.x * blockDim.x + threadIdx.x; i4 < n4;
         i4 += gridDim.x * blockDim.x) {
        float4 p = pred4[i4];
        int base = i4 * 4;
        float pv[4] = {p.x, p.y, p.z, p.w};
        #pragma unroll
        for (int j = 0; j < 4; j++) {
            int b = batch_of(base + j, o);
            atomicAdd(&g_hist1[b * NBIN + (f2key(pv[j]) >> 16)], 1u);
        }
    }
}

// -------- pass 2: low-16-bit histogram of in-selected-bin elements ---------
__global__ void k_hist2(const float4* __restrict__ pred4, int n4) {
    __shared__ int soff[MAXB + 1];
    __shared__ unsigned ssel[MAXB];
    if (threadIdx.x <= MAXB) soff[threadIdx.x] = g_off[threadIdx.x];
    if (threadIdx.x < MAXB)  ssel[threadIdx.x] = g_selBin[threadIdx.x];
    __syncthreads();
    int o[MAXB + 1];
    #pragma unroll
    for (int k = 0; k <= MAXB; k++) o[k] = soff[k];

    for (int i4 = blockIdx.x * blockDim.x + threadIdx.x; i4 < n4;
         i4 += gridDim.x * blockDim.x) {
        float4 p = pred4[i4];
        int base = i4 * 4;
        float pv[4] = {p.x, p.y, p.z, p.w};
        #pragma unroll
        for (int j = 0; j < 4; j++) {
            int b = batch_of(base + j, o);
            unsigned key = f2key(pv[j]);
            if ((key >> 16) == ssel[b])
                atomicAdd(&g_hist2[b * NBIN + (key & 0xFFFFu)], 1u);
        }
    }
}

// -------- fused coarse + walk: 512 blocks; last 8 walk one batch each ------
__global__ void k_coarse_walk(int level, const int* __restrict__ tgt) {
    const unsigned* hist = (level == 1) ? g_hist1 : g_hist2;
    int tid = threadIdx.x;

    // ---- coarse: segment sum for (batch, seg) of this block ----
    {
        int b = blockIdx.x >> 6;
        int s = blockIdx.x & 63;
        const uint4* h4 = (const uint4*)&hist[b * NBIN + s * SEGBINS];
        uint4 v = h4[tid];
        unsigned sum = v.x + v.y + v.z + v.w;
        #pragma unroll
        for (int d = 16; d > 0; d >>= 1)
            sum += __shfl_down_sync(0xFFFFFFFFu, sum, d);
        __shared__ unsigned ws[8];
        if ((tid & 31) == 0) ws[tid >> 5] = sum;
        __syncthreads();
        if (tid == 0) {
            unsigned t = 0;
            #pragma unroll
            for (int w = 0; w < 8; w++) t += ws[w];
            g_seg[b * NSEG + s] = t;
        }
        __syncthreads();
    }

    // ---- ticket: last 8 blocks become walkers (one batch each) ----
    __threadfence();
    __shared__ unsigned my_t;
    if (tid == 0) my_t = atomicAdd(&g_ticket, 1u) + 1u;
    __syncthreads();
    unsigned target = (unsigned)level * 512u;
    if (my_t + 8u <= target) return;
    int b = (int)(target - my_t);  // 0..7
    if (tid == 0) {
        while (*(volatile unsigned*)&g_ticket < target) {}
    }
    __syncthreads();
    __threadfence();

    // ---- walk batch b (parallel scan-select) ----
    __shared__ unsigned wsum[8];
    __shared__ int sact;
    __shared__ unsigned srank;
    __shared__ int ssegi;
    __shared__ unsigned srank2;

    if (tid == 0) {
        long long rank;
        int act;
        if (level == 1) {
            int nn = g_off[b + 1] - g_off[b];
            int t = tgt[b];
            act = (nn > t);
            rank = (long long)nn - t - 1;
        } else {
            act = g_active[b];
            rank = (long long)g_selRank[b];
        }
        sact = act;
        srank = (unsigned)rank;
    }
    __syncthreads();
    if (!sact) {
        if (tid == 0) {
            if (level == 1) {
                g_active[b] = 0;
                g_selBin[b] = 0xFFFFFFFFu;  // matches nothing in pass 2
                g_selRank[b] = 0;
            } else {
                g_threshKey[b] = 0u;  // every real key > 0 -> keep all
            }
        }
        return;
    }

    // level A: pick segment among 64 seg-sums
    unsigned v = (tid < NSEG) ? g_seg[b * NSEG + tid] : 0u;
    unsigned e = scan_excl(v, tid, wsum);
    unsigned r = srank;
    if (r >= e && r < e + v) { ssegi = tid; srank2 = r - e; }
    __syncthreads();

    // level B: pick bin among 1024 bins of the segment (4/thread)
    const uint4* h4 = (const uint4*)&hist[b * NBIN + ssegi * SEGBINS];
    uint4 q = h4[tid];
    unsigned v2 = q.x + q.y + q.z + q.w;
    unsigned e2 = scan_excl(v2, tid, wsum);
    unsigned r2 = srank2;
    if (r2 >= e2 && r2 < e2 + v2) {
        unsigned rr = r2 - e2;
        unsigned bvals[4] = {q.x, q.y, q.z, q.w};
        int j = 0;
        while (rr >= bvals[j]) { rr -= bvals[j]; j++; }
        unsigned bin = (unsigned)(ssegi * SEGBINS + tid * 4 + j);
        if (level == 1) {
            g_selBin[b] = bin;
            g_selRank[b] = rr;
            g_active[b] = 1;
        } else {
            g_threshKey[b] = (g_selBin[b] << 16) | bin;
        }
    }
}

// -------- streaming prune: 4 x float4 per thread, skip dropped reads -------
__global__ void k_prune(const float4* __restrict__ fea4,
                        const float* __restrict__ pred,
                        float4* __restrict__ out4,
                        float* __restrict__ out_keep,
                        int nrows, int writeKeep) {
    __shared__ unsigned sthr[MAXB];
    __shared__ int soff[MAXB + 1];
    if (threadIdx.x < MAXB) sthr[threadIdx.x] = g_threshKey[threadIdx.x];
    if (threadIdx.x >= 32 && threadIdx.x <= 32 + MAXB)
        soff[threadIdx.x - 32] = g_off[threadIdx.x - 32];
    __syncthreads();

    int gid = blockIdx.x * blockDim.x + threadIdx.x;

    // fold scratch re-zero for next invocation (graph replay determinism)
    {
        const int ZW = (MAXB * NBIN) / 4;  // uint4 words per hist
        if (gid < ZW) {
            ((uint4*)g_hist1)[gid] = make_uint4(0u, 0u, 0u, 0u);
        } else if (gid < 2 * ZW) {
            ((uint4*)g_hist2)[gid - ZW] = make_uint4(0u, 0u, 0u, 0u);
        } else if (gid == 2 * ZW) {
            g_ticket = 0u;
        }
    }

    int row = gid >> 2;  // 4 threads per 64-wide row (4 float4 each)
    if (row >= nrows) return;
    int o[MAXB + 1];
    #pragma unroll
    for (int k = 0; k <= MAXB; k++) o[k] = soff[k];
    int b = batch_of(row, o);
    unsigned key = f2key(pred[row]);
    bool keep = key > sthr[b];

    float4 v0 = make_float4(0.f, 0.f, 0.f, 0.f);
    float4 v1 = v0, v2 = v0, v3 = v0;
    if (keep) {  // dropped rows: no fea read (output is zeros there)
        v0 = __ldcs(&fea4[4 * gid + 0]);
        v1 = __ldcs(&fea4[4 * gid + 1]);
        v2 = __ldcs(&fea4[4 * gid + 2]);
        v3 = __ldcs(&fea4[4 * gid + 3]);
    }
    __stcs(&out4[4 * gid + 0], v0);
    __stcs(&out4[4 * gid + 1], v1);
    __stcs(&out4[4 * gid + 2], v2);
    __stcs(&out4[4 * gid + 3], v3);
    if (writeKeep && ((gid & 3) == 0)) out_keep[row] = keep ? 1.0f : 0.0f;
}

extern "C" void kernel_launch(void* const* d_in, const int* in_sizes, int n_in,
                              void* d_out, int out_size) {
    const float* fea  = (const float*)d_in[0];
    const float* pred = (const float*)d_in[1];
    const int*   bid  = (const int*)d_in[2];
    const int*   tgt  = (const int*)d_in[3];
    const int n = in_sizes[1];      // N points
    const int C = in_sizes[0] / n;  // 64

    float* out_fea  = (float*)d_out;
    int writeKeep = (out_size >= n * C + n) ? 1 : 0;
    float* out_keep = out_fea + (size_t)n * C;

    k_bounds<<<1, 32>>>(bid, n);
    int n4 = n / 4;
    k_hist1<<<(n4 + 255) / 256, 256>>>((const float4*)pred, n4);
    k_coarse_walk<<<MAXB * NSEG, 256>>>(1, tgt);
    k_hist2<<<(n4 + 255) / 256, 256>>>((const float4*)pred, n4);
    k_coarse_walk<<<MAXB * NSEG, 256>>>(2, tgt);

    int nthreads = n * 4;  // 4 threads per row
    k_prune<<<(nthreads + 255) / 256, 256>>>((const float4*)fea, pred,
                                             (float4*)d_out, out_keep,
                                             n, writeKeep);
}

// round 9
// speedup vs baseline: 1.0771x; 1.0771x over previous
#include <cuda_runtime.h>
#include <cstdint>

// ---------------------------------------------------------------------------
// GenerativeUpsample: per-batch kth-smallest threshold on pred, prune fea.
//   fea:  [N, 64] f32   d_in[0]
//   pred: [N, 1]  f32   d_in[1]
//   bid:  [N]     i32   d_in[2]  (sorted)
//   tgt:  [B]     i32   d_in[3]
// out: [N*64] pruned fea, then (if room) [N] keep as 0/1 float.
//
// Exact 2-level (16+16 bit) radix select on monotone uint key of pred.
// coarse+walk fused via ticket; prune is ILP=2 (MLP_p1 kept low to avoid
// cross-CTA L1tex-queue tail spread that regressed the ILP=4 variant).
// ---------------------------------------------------------------------------

#define MAXB 8
#define NBIN 65536
#define NSEG 64
#define SEGBINS 1024

__device__ __align__(16) unsigned g_hist1[MAXB * NBIN];
__device__ __align__(16) unsigned g_hist2[MAXB * NBIN];
__device__ unsigned g_seg[MAXB * NSEG];
__device__ unsigned g_ticket;          // monotone within one invocation
__device__ int      g_off[MAXB + 1];
__device__ unsigned g_selBin[MAXB];
__device__ unsigned g_selRank[MAXB];
__device__ int      g_active[MAXB];
__device__ unsigned g_threshKey[MAXB];

__device__ __forceinline__ unsigned f2key(float f) {
    unsigned u = __float_as_uint(f);
    return (u & 0x80000000u) ? ~u : (u | 0x80000000u);
}

__device__ __forceinline__ int batch_of(int i, const int* o) {
    int b = 0;
    #pragma unroll
    for (int k = 1; k < MAXB; k++) b += (i >= o[k]);
    return b;
}

// block-wide (256 thr) exclusive scan; wsum = 8-word smem scratch.
__device__ __forceinline__ unsigned scan_excl(unsigned val, int tid,
                                              unsigned* wsum) {
    int lane = tid & 31, wid = tid >> 5;
    unsigned x = val;
    #pragma unroll
    for (int d = 1; d < 32; d <<= 1) {
        unsigned y = __shfl_up_sync(0xFFFFFFFFu, x, d);
        if (lane >= d) x += y;
    }
    if (lane == 31) wsum[wid] = x;
    __syncthreads();
    if (tid == 0) {
        unsigned a = 0;
        #pragma unroll
        for (int w = 0; w < 8; w++) { unsigned t = wsum[w]; wsum[w] = a; a += t; }
    }
    __syncthreads();
    return wsum[wid] + x - val;
}

// -------- batch boundaries via binary search (bids sorted) -----------------
__global__ void k_bounds(const int* __restrict__ bid, int n) {
    int t = threadIdx.x;
    if (t > MAXB) return;
    if (t == MAXB) { g_off[MAXB] = n; return; }
    int lo = 0, hi = n;
    while (lo < hi) {
        int mid = (lo + hi) >> 1;
        if (bid[mid] < t) lo = mid + 1; else hi = mid;
    }
    g_off[t] = lo;
}

// -------- pass 1: top-16-bit histogram, float4 loads -----------------------
__global__ void k_hist1(const float4* __restrict__ pred4, int n4) {
    __shared__ int soff[MAXB + 1];
    if (threadIdx.x <= MAXB) soff[threadIdx.x] = g_off[threadIdx.x];
    __syncthreads();
    int o[MAXB + 1];
    #pragma unroll
    for (int k = 0; k <= MAXB; k++) o[k] = soff[k];

    for (int i4 = blockIdx.x * blockDim.x + threadIdx.x; i4 < n4;
         i4 += gridDim.x * blockDim.x) {
        float4 p = pred4[i4];
        int base = i4 * 4;
        float pv[4] = {p.x, p.y, p.z, p.w};
        #pragma unroll
        for (int j = 0; j < 4; j++) {
            int b = batch_of(base + j, o);
            atomicAdd(&g_hist1[b * NBIN + (f2key(pv[j]) >> 16)], 1u);
        }
    }
}

// -------- pass 2: low-16-bit histogram of in-selected-bin elements ---------
__global__ void k_hist2(const float4* __restrict__ pred4, int n4) {
    __shared__ int soff[MAXB + 1];
    __shared__ unsigned ssel[MAXB];
    if (threadIdx.x <= MAXB) soff[threadIdx.x] = g_off[threadIdx.x];
    if (threadIdx.x < MAXB)  ssel[threadIdx.x] = g_selBin[threadIdx.x];
    __syncthreads();
    int o[MAXB + 1];
    #pragma unroll
    for (int k = 0; k <= MAXB; k++) o[k] = soff[k];

    for (int i4 = blockIdx.x * blockDim.x + threadIdx.x; i4 < n4;
         i4 += gridDim.x * blockDim.x) {
        float4 p = pred4[i4];
        int base = i4 * 4;
        float pv[4] = {p.x, p.y, p.z, p.w};
        #pragma unroll
        for (int j = 0; j < 4; j++) {
            int b = batch_of(base + j, o);
            unsigned key = f2key(pv[j]);
            if ((key >> 16) == ssel[b])
                atomicAdd(&g_hist2[b * NBIN + (key & 0xFFFFu)], 1u);
        }
    }
}

// -------- fused coarse + walk: 512 blocks; last 8 walk one batch each ------
__global__ void k_coarse_walk(int level, const int* __restrict__ tgt) {
    const unsigned* hist = (level == 1) ? g_hist1 : g_hist2;
    int tid = threadIdx.x;

    // ---- coarse: segment sum for (batch, seg) of this block ----
    {
        int b = blockIdx.x >> 6;
        int s = blockIdx.x & 63;
        const uint4* h4 = (const uint4*)&hist[b * NBIN + s * SEGBINS];
        uint4 v = h4[tid];
        unsigned sum = v.x + v.y + v.z + v.w;
        #pragma unroll
        for (int d = 16; d > 0; d >>= 1)
            sum += __shfl_down_sync(0xFFFFFFFFu, sum, d);
        __shared__ unsigned ws[8];
        if ((tid & 31) == 0) ws[tid >> 5] = sum;
        __syncthreads();
        if (tid == 0) {
            unsigned t = 0;
            #pragma unroll
            for (int w = 0; w < 8; w++) t += ws[w];
            g_seg[b * NSEG + s] = t;
        }
        __syncthreads();
    }

    // ---- ticket: last 8 blocks become walkers (one batch each) ----
    __threadfence();
    __shared__ unsigned my_t;
    if (tid == 0) my_t = atomicAdd(&g_ticket, 1u) + 1u;
    __syncthreads();
    unsigned target = (unsigned)level * 512u;
    if (my_t + 8u <= target) return;
    int b = (int)(target - my_t);  // 0..7
    if (tid == 0) {
        while (*(volatile unsigned*)&g_ticket < target) {}
    }
    __syncthreads();
    __threadfence();

    // ---- walk batch b (parallel scan-select) ----
    __shared__ unsigned wsum[8];
    __shared__ int sact;
    __shared__ unsigned srank;
    __shared__ int ssegi;
    __shared__ unsigned srank2;

    if (tid == 0) {
        long long rank;
        int act;
        if (level == 1) {
            int nn = g_off[b + 1] - g_off[b];
            int t = tgt[b];
            act = (nn > t);
            rank = (long long)nn - t - 1;
        } else {
            act = g_active[b];
            rank = (long long)g_selRank[b];
        }
        sact = act;
        srank = (unsigned)rank;
    }
    __syncthreads();
    if (!sact) {
        if (tid == 0) {
            if (level == 1) {
                g_active[b] = 0;
                g_selBin[b] = 0xFFFFFFFFu;  // matches nothing in pass 2
                g_selRank[b] = 0;
            } else {
                g_threshKey[b] = 0u;  // every real key > 0 -> keep all
            }
        }
        return;
    }

    // level A: pick segment among 64 seg-sums
    unsigned v = (tid < NSEG) ? g_seg[b * NSEG + tid] : 0u;
    unsigned e = scan_excl(v, tid, wsum);
    unsigned r = srank;
    if (r >= e && r < e + v) { ssegi = tid; srank2 = r - e; }
    __syncthreads();

    // level B: pick bin among 1024 bins of the segment (4/thread)
    const uint4* h4 = (const uint4*)&hist[b * NBIN + ssegi * SEGBINS];
    uint4 q = h4[tid];
    unsigned v2 = q.x + q.y + q.z + q.w;
    unsigned e2 = scan_excl(v2, tid, wsum);
    unsigned r2 = srank2;
    if (r2 >= e2 && r2 < e2 + v2) {
        unsigned rr = r2 - e2;
        unsigned bvals[4] = {q.x, q.y, q.z, q.w};
        int j = 0;
        while (rr >= bvals[j]) { rr -= bvals[j]; j++; }
        unsigned bin = (unsigned)(ssegi * SEGBINS + tid * 4 + j);
        if (level == 1) {
            g_selBin[b] = bin;
            g_selRank[b] = rr;
            g_active[b] = 1;
        } else {
            g_threshKey[b] = (g_selBin[b] << 16) | bin;
        }
    }
}

// -------- streaming prune: ILP=2, skip fea reads for dropped rows ----------
__global__ void k_prune(const float4* __restrict__ fea4,
                        const float* __restrict__ pred,
                        float4* __restrict__ out4,
                        float* __restrict__ out_keep,
                        int total2, int writeKeep) {
    __shared__ unsigned sthr[MAXB];
    __shared__ int soff[MAXB + 1];
    if (threadIdx.x < MAXB) sthr[threadIdx.x] = g_threshKey[threadIdx.x];
    if (threadIdx.x >= 32 && threadIdx.x <= 32 + MAXB)
        soff[threadIdx.x - 32] = g_off[threadIdx.x - 32];
    __syncthreads();

    int gid = blockIdx.x * blockDim.x + threadIdx.x;

    // fold scratch re-zero for next invocation (graph replay determinism)
    {
        const int ZW = (MAXB * NBIN) / 4;  // uint4 words per hist
        if (gid < ZW) {
            ((uint4*)g_hist1)[gid] = make_uint4(0u, 0u, 0u, 0u);
        } else if (gid < 2 * ZW) {
            ((uint4*)g_hist2)[gid - ZW] = make_uint4(0u, 0u, 0u, 0u);
        } else if (gid == 2 * ZW) {
            g_ticket = 0u;
        }
    }

    if (gid >= total2) return;
    int row = gid >> 3;  // 8 threads per 64-wide row (2 float4 each)
    int o[MAXB + 1];
    #pragma unroll
    for (int k = 0; k <= MAXB; k++) o[k] = soff[k];
    int b = batch_of(row, o);
    unsigned key = f2key(pred[row]);
    bool keep = key > sthr[b];

    float4 v0 = make_float4(0.f, 0.f, 0.f, 0.f);
    float4 v1 = v0;
    if (keep) {  // dropped rows: no fea read (output is zeros there)
        v0 = __ldcs(&fea4[2 * gid]);
        v1 = __ldcs(&fea4[2 * gid + 1]);
    }
    __stcs(&out4[2 * gid], v0);
    __stcs(&out4[2 * gid + 1], v1);
    if (writeKeep && ((gid & 7) == 0)) out_keep[row] = keep ? 1.0f : 0.0f;
}

extern "C" void kernel_launch(void* const* d_in, const int* in_sizes, int n_in,
                              void* d_out, int out_size) {
    const float* fea  = (const float*)d_in[0];
    const float* pred = (const float*)d_in[1];
    const int*   bid  = (const int*)d_in[2];
    const int*   tgt  = (const int*)d_in[3];
    const int n = in_sizes[1];      // N points
    const int C = in_sizes[0] / n;  // 64

    float* out_fea  = (float*)d_out;
    int writeKeep = (out_size >= n * C + n) ? 1 : 0;
    float* out_keep = out_fea + (size_t)n * C;

    k_bounds<<<1, 32>>>(bid, n);
    int n4 = n / 4;
    k_hist1<<<(n4 + 255) / 256, 256>>>((const float4*)pred, n4);
    k_coarse_walk<<<MAXB * NSEG, 256>>>(1, tgt);
    k_hist2<<<(n4 + 255) / 256, 256>>>((const float4*)pred, n4);
    k_coarse_walk<<<MAXB * NSEG, 256>>>(2, tgt);

    int total2 = n * (C / 8);  // threads, 2 float4 each
    k_prune<<<(total2 + 511) / 512, 512>>>((const float4*)fea, pred,
                                           (float4*)d_out, out_keep,
                                           total2, writeKeep);
}